// round 4
// baseline (speedup 1.0000x reference)
#include <cuda_runtime.h>
#include <cuda_bf16.h>
#include <cstddef>

// Sorted segment-sum: feat[1e6, 128] fp32 -> out[4096, 128] fp32.
// One warp per contiguous chain of 8-row tiles, tiles distributed EXACTLY
// evenly across all chains. Grid sized for ~8 waves so CLC work-stealing
// smooths the cross-CTA completion spread at each wave tail. Hot loop:
// 8 rows/iter, branch-free front-batched streaming loads (2x int4 seg +
// 8x float4 feat => MLP ~10/warp). Sortedness: last id in batch == cur
// => whole batch == cur. Flushes (chain ends + segment boundaries, ~42K
// total) are atomicAdds into the 2MB L2-resident output - negligible
// DRAM-side traffic.

#define WARPS_PER_BLOCK 8
#define THREADS (WARPS_PER_BLOCK * 32)
#define GRID_BLOCKS 4736   // 148 SMs * 32 -> 8 waves at 4 resident blocks/SM
#define D_FEAT 128

__global__ void zero_out_kernel(float4* __restrict__ out, int n4) {
    int i = blockIdx.x * blockDim.x + threadIdx.x;
    if (i < n4) out[i] = make_float4(0.f, 0.f, 0.f, 0.f);
}

__device__ __forceinline__ float4 f4add(float4 a, float4 b) {
    return make_float4(a.x + b.x, a.y + b.y, a.z + b.z, a.w + b.w);
}

__global__ __launch_bounds__(THREADS, 4)
void segsum_kernel(const float4* __restrict__ feat4,
                   const int* __restrict__ seg,
                   float* __restrict__ out,
                   int n_rows) {
    const int warp = threadIdx.x >> 5;
    const int lane = threadIdx.x & 31;

    const long n_chains = (long)GRID_BLOCKS * WARPS_PER_BLOCK;
    const long n_tiles = n_rows >> 3;            // full 8-row tiles
    const long chain = (long)blockIdx.x * WARPS_PER_BLOCK + warp;

    // Balanced split: chain c owns tiles [c*n_tiles/n_chains, (c+1)*n_tiles/n_chains)
    long t0 = (chain * n_tiles) / n_chains;
    long t1 = ((chain + 1) * n_tiles) / n_chains;
    long r0 = t0 << 3;
    long r1 = t1 << 3;
    // Last chain also takes the (n_rows % 8) remainder rows.
    if (chain == n_chains - 1) r1 = n_rows;
    if (r0 >= r1) return;

    float4 acc = make_float4(0.f, 0.f, 0.f, 0.f);
    int cur = __ldcs(seg + r0);

    long r = r0;
    // ---------- hot loop: branch-free loads, 8 rows / iter ----------
    for (; r + 8 <= r1; r += 8) {
        const int4 sA = __ldcs(reinterpret_cast<const int4*>(seg + r));
        const int4 sB = __ldcs(reinterpret_cast<const int4*>(seg + r + 4));
        const float4* base = feat4 + (size_t)r * (D_FEAT / 4) + lane;
        const float4 v0 = __ldcs(base + 0 * 32);
        const float4 v1 = __ldcs(base + 1 * 32);
        const float4 v2 = __ldcs(base + 2 * 32);
        const float4 v3 = __ldcs(base + 3 * 32);
        const float4 v4 = __ldcs(base + 4 * 32);
        const float4 v5 = __ldcs(base + 5 * 32);
        const float4 v6 = __ldcs(base + 6 * 32);
        const float4 v7 = __ldcs(base + 7 * 32);

        if (sB.w == cur) {
            // sorted ids: last == cur  =>  all 8 == cur
            float4 t0s = f4add(f4add(v0, v1), f4add(v2, v3));
            float4 t1s = f4add(f4add(v4, v5), f4add(v6, v7));
            acc = f4add(acc, f4add(t0s, t1s));
        } else {
            // cold path: segment boundary inside this batch
            int s[8] = {sA.x, sA.y, sA.z, sA.w, sB.x, sB.y, sB.z, sB.w};
            float4 v[8] = {v0, v1, v2, v3, v4, v5, v6, v7};
            #pragma unroll
            for (int i = 0; i < 8; i++) {
                if (s[i] != cur) {
                    float* dst = out + (size_t)cur * D_FEAT + lane * 4;
                    atomicAdd(dst + 0, acc.x);
                    atomicAdd(dst + 1, acc.y);
                    atomicAdd(dst + 2, acc.z);
                    atomicAdd(dst + 3, acc.w);
                    acc = make_float4(0.f, 0.f, 0.f, 0.f);
                    cur = s[i];
                }
                acc = f4add(acc, v[i]);
            }
        }
    }
    // ---------- scalar tail (only last chain, if n_rows % 8 != 0) ----------
    for (; r < r1; ++r) {
        int s = __ldcs(seg + r);
        float4 v = __ldcs(feat4 + (size_t)r * (D_FEAT / 4) + lane);
        if (s != cur) {
            float* dst = out + (size_t)cur * D_FEAT + lane * 4;
            atomicAdd(dst + 0, acc.x);
            atomicAdd(dst + 1, acc.y);
            atomicAdd(dst + 2, acc.z);
            atomicAdd(dst + 3, acc.w);
            acc = make_float4(0.f, 0.f, 0.f, 0.f);
            cur = s;
        }
        acc = f4add(acc, v);
    }

    float* dst = out + (size_t)cur * D_FEAT + lane * 4;
    atomicAdd(dst + 0, acc.x);
    atomicAdd(dst + 1, acc.y);
    atomicAdd(dst + 2, acc.z);
    atomicAdd(dst + 3, acc.w);
}

extern "C" void kernel_launch(void* const* d_in, const int* in_sizes, int n_in,
                              void* d_out, int out_size) {
    const float* feat = (const float*)d_in[0];
    const int* seg = (const int*)d_in[1];
    float* out = (float*)d_out;

    const int n_rows = in_sizes[0] / D_FEAT;  // 1,000,000
    const int n4 = out_size / 4;              // 131072

    zero_out_kernel<<<(n4 + 255) / 256, 256>>>((float4*)out, n4);
    segsum_kernel<<<GRID_BLOCKS, THREADS>>>((const float4*)feat, seg, out, n_rows);
}